// round 15
// baseline (speedup 1.0000x reference)
#include <cuda_runtime.h>
#include <cuda_fp16.h>
#include <cstdint>
#include <cstddef>

// Shapes: x[32,64,25,1024], W[25,192,64], A[3,25,25], out[32,64,25,1024]
// Stage 1 (HMMA fp16): Yh[c*75 + k*25 + w][j] = sum_c' W[w,c*3+k,c'] x[n,c',w,t]
//   v3: 256-j per CTA (4 x 64-j halves), W converted once, X reg-prefetched,
//       sS staging ping-ponged -> 1 sync/half, Y-copy overlaps next MMA.
// Stage 2 (HMMA fp16, single-pass A): out[n,c,v,t] = sum_r A[v,r]*Yh[c*75+r][j]
//   (R14 version: double-buffered sY, 1 sync/phase -- at its BW floor)

#define NB 32
#define CC 64
#define VV 25
#define TT 1024
#define KK 3
#define OO 192
#define NT 32768
#define WS1 72            /* stage1 padded row stride (halves) */

// 315 MB fp16 scratch for Y.
__device__ unsigned short g_Yh[(size_t)VV * OO * NT];

// stage1 smem layout (dynamic, 101376 B -> 2 CTAs/SM)
#define S1_W   0
#define S1_X0  27648
#define S1_X1  36864
#define S1_S0  46080
#define S1_S1  73728
#define S1_TOT 101376

// stage2 smem layout (dynamic, 49152 B)
#define AST    88
#define YST    136
#define YBUF   (80 * YST * 2)     /* 21760 */
#define S2_A   0
#define S2_Y0  5632
#define S2_TOT (5632 + 2 * YBUF)  /* 49152 */

// ---------------------------------------------------------------------------
__device__ __forceinline__ uint32_t smem_u32(const void* p) {
    uint32_t a;
    asm("{ .reg .u64 t; cvta.to.shared.u64 t, %1; cvt.u32.u64 %0, t; }"
        : "=r"(a) : "l"(p));
    return a;
}
__device__ __forceinline__ void ldm_x4(uint32_t a[4], uint32_t addr) {
    asm volatile("ldmatrix.sync.aligned.m8n8.x4.shared.b16 {%0,%1,%2,%3}, [%4];"
        : "=r"(a[0]), "=r"(a[1]), "=r"(a[2]), "=r"(a[3]) : "r"(addr));
}
__device__ __forceinline__ void ldm_x2t(uint32_t b[2], uint32_t addr) {
    asm volatile("ldmatrix.sync.aligned.m8n8.x2.trans.shared.b16 {%0,%1}, [%2];"
        : "=r"(b[0]), "=r"(b[1]) : "r"(addr));
}
__device__ __forceinline__ void ldm_x4t(uint32_t a[4], uint32_t addr) {
    asm volatile("ldmatrix.sync.aligned.m8n8.x4.trans.shared.b16 {%0,%1,%2,%3}, [%4];"
        : "=r"(a[0]), "=r"(a[1]), "=r"(a[2]), "=r"(a[3]) : "r"(addr));
}
__device__ __forceinline__ void mma_f16(float c[4], const uint32_t a[4],
                                        const uint32_t b[2]) {
    asm volatile("mma.sync.aligned.m16n8k16.row.col.f32.f16.f16.f32 "
        "{%0,%1,%2,%3}, {%4,%5,%6,%7}, {%8,%9}, {%0,%1,%2,%3};"
        : "+f"(c[0]), "+f"(c[1]), "+f"(c[2]), "+f"(c[3])
        : "r"(a[0]), "r"(a[1]), "r"(a[2]), "r"(a[3]), "r"(b[0]), "r"(b[1]));
}

// ---------------------------------------------------------------------------
// Stage 1 v3
// ---------------------------------------------------------------------------
__global__ __launch_bounds__(256, 2) void stage1_mma(
    const float* __restrict__ x, const float* __restrict__ Wg)
{
    extern __shared__ char sm[];
    const uint32_t sb = smem_u32(sm);

    const int tid = threadIdx.x;
    const int w   = blockIdx.y;
    const int j0  = blockIdx.x * 256;
    const int n   = j0 >> 10;           // 256 | 1024: never crosses n
    const int t0  = j0 & 1023;

    // ---- W[w] 192x64 fp32 -> fp16 (once per 256 j) ----
    {
        const float* wg = Wg + (size_t)w * OO * 64;
        #pragma unroll
        for (int i = 0; i < 24; ++i) {
            int idx = tid + i * 256;
            int o = idx >> 5, cp = idx & 31;
            float2 wv = *(const float2*)(wg + (size_t)o * 64 + cp * 2);
            *(__half2*)(sm + S1_W + (o * WS1 + cp * 2) * 2) =
                __floats2half2_rn(wv.x, wv.y);
        }
    }
    const float* xb = x + (size_t)n * CC * VV * TT + (size_t)w * TT + t0;
    // ---- X half 0 -> XB0 ----
    {
        #pragma unroll
        for (int i = 0; i < 8; ++i) {
            int idx = tid + i * 256;
            int r = idx >> 5, cp = idx & 31;
            float2 xv = *(const float2*)(xb + (size_t)r * (VV * TT) + cp * 2);
            *(__half2*)(sm + S1_X0 + (r * WS1 + cp * 2) * 2) =
                __floats2half2_rn(xv.x, xv.y);
        }
    }
    __syncthreads();

    const int wid = tid >> 5, lane = tid & 31;
    const int m0 = (wid >> 1) * 48, n0 = (wid & 1) * 32;
    const int arow = lane & 15, acolb = (lane >> 4) * 8, brow = lane & 15;
    const int r4 = lane >> 2, q4 = lane & 3;

    #pragma unroll
    for (int h = 0; h < 4; ++h) {
        const uint32_t XB = sb + ((h & 1) ? S1_X1 : S1_X0);
        const int SS = (h & 1) ? S1_S1 : S1_S0;

        // prefetch X half h+1 into registers (overlaps MMA)
        float2 xr[8];
        if (h < 3) {
            const float* xh = xb + (h + 1) * 64;
            #pragma unroll
            for (int i = 0; i < 8; ++i) {
                int idx = tid + i * 256;
                int r = idx >> 5, cp = idx & 31;
                xr[i] = *(const float2*)(xh + (size_t)r * (VV * TT) + cp * 2);
            }
        }

        float acc[3][4][4] = {};
        #pragma unroll
        for (int ks = 0; ks < 4; ++ks) {
            uint32_t Af[3][4], Bf[4][2];
            #pragma unroll
            for (int i = 0; i < 3; ++i)
                ldm_x4(Af[i], sb + S1_W + (uint32_t)(((m0 + 16 * i + arow) * WS1
                                                      + ks * 16 + acolb) * 2));
            #pragma unroll
            for (int t = 0; t < 4; ++t)
                ldm_x2t(Bf[t], XB + (uint32_t)(((ks * 16 + brow) * WS1
                                                + n0 + 8 * t) * 2));
            #pragma unroll
            for (int i = 0; i < 3; ++i)
                #pragma unroll
                for (int t = 0; t < 4; ++t)
                    mma_f16(acc[i][t], Af[i], Bf[t]);
        }

        // stage D -> sS(h&1)
        #pragma unroll
        for (int i = 0; i < 3; ++i)
            #pragma unroll
            for (int t = 0; t < 4; ++t) {
                int row = m0 + 16 * i + r4;
                int col = n0 + 8 * t + 2 * q4;
                *(half2*)(sm + SS + (row * WS1 + col) * 2) =
                    __floats2half2_rn(acc[i][t][0], acc[i][t][1]);
                *(half2*)(sm + SS + ((row + 8) * WS1 + col) * 2) =
                    __floats2half2_rn(acc[i][t][2], acc[i][t][3]);
            }

        // store prefetched X half h+1 into the other X buffer
        if (h < 3) {
            const int XD = (h & 1) ? S1_X0 : S1_X1;
            #pragma unroll
            for (int i = 0; i < 8; ++i) {
                int idx = tid + i * 256;
                int r = idx >> 5, cp = idx & 31;
                *(__half2*)(sm + XD + (r * WS1 + cp * 2) * 2) =
                    __floats2half2_rn(xr[i].x, xr[i].y);
            }
        }
        __syncthreads();   // staging + X(h+1) visible; copy(h-1) done (prog order)

        // coalesced copy sS(h&1) -> Y columns j0 + h*64 (overlaps next MMA)
        #pragma unroll
        for (int i = 0; i < 24; ++i) {
            int idx = tid + i * 256;
            int row = idx >> 5;
            int u   = idx & 31;
            uint32_t val = *(uint32_t*)(sm + SS + row * (WS1 * 2) + u * 4);
            int cch = row / 3;
            int kk  = row - 3 * cch;
            size_t yrow = (size_t)(cch * 75 + kk * VV + w);
            *(uint32_t*)((char*)g_Yh + (yrow * NT + j0 + h * 64) * 2 + u * 4) = val;
        }
    }
}

// ---------------------------------------------------------------------------
// Stage 2 (unchanged from R14): single-pass fp16 A, double-buffered sY.
// ---------------------------------------------------------------------------
#define JT 128

__global__ __launch_bounds__(256) void stage2_mma(
    const float* __restrict__ Ag, float* __restrict__ out)
{
    extern __shared__ char sm[];
    const uint32_t sb = smem_u32(sm);
    __half* sA = (__half*)(sm + S2_A);

    const int tid = threadIdx.x;
    const int j0  = blockIdx.x * JT;
    const int c0  = blockIdx.y * 8;
    const int n   = j0 >> 10;
    const int tt0 = j0 & 1023;

    for (int i = tid; i < 80 * 32; i += 256) {
        int r = i >> 5, v = i & 31;
        float a = (r < 75 && v < 25) ? Ag[r * 25 + v] : 0.0f;
        sA[v * AST + r] = __float2half_rn(a);
    }

    const int wid  = tid >> 5, lane = tid & 31;
    const int jw   = wid * 16;
    const int arow = lane & 15, acolb = (lane >> 4) * 8;
    const int brow = lane & 15, bcol = (lane >> 4) * 8;
    const int r4   = lane >> 2, q2 = (lane & 3) * 2;

    int lr[5], lch[5];
    #pragma unroll
    for (int s = 0; s < 5; ++s) {
        int i = tid + s * 256;
        lr[s]  = i >> 4;
        lch[s] = i & 15;
    }

    uint4 pf[5];
    {
        const char* yb = (const char*)g_Yh + ((size_t)c0 * 75 * NT + j0) * 2;
        #pragma unroll
        for (int s = 0; s < 5; ++s)
            pf[s] = (lr[s] < 75)
                ? *(const uint4*)(yb + (size_t)lr[s] * NT * 2 + lch[s] * 16)
                : make_uint4(0u, 0u, 0u, 0u);
    }
    #pragma unroll
    for (int s = 0; s < 5; ++s)
        *(uint4*)(sm + S2_Y0 + (lr[s] * YST + lch[s] * 8) * 2) = pf[s];

    for (int ci = 0; ci < 8; ++ci) {
        const int c = c0 + ci;
        const uint32_t YB = sb + S2_Y0 + (uint32_t)((ci & 1) * YBUF);

        __syncthreads();

        if (ci < 7) {
            const char* yb = (const char*)g_Yh
                           + ((size_t)(c + 1) * 75 * NT + j0) * 2;
            #pragma unroll
            for (int s = 0; s < 5; ++s)
                pf[s] = (lr[s] < 75)
                    ? *(const uint4*)(yb + (size_t)lr[s] * NT * 2 + lch[s] * 16)
                    : make_uint4(0u, 0u, 0u, 0u);
        }

        float acc[2][2][4] = {};
        #pragma unroll
        for (int ks = 0; ks < 5; ++ks) {
            uint32_t a0[4], a1[4], Bf[4];
            ldm_x4(a0, sb + S2_A + (uint32_t)(((arow) * AST
                                               + ks * 16 + acolb) * 2));
            ldm_x4(a1, sb + S2_A + (uint32_t)(((16 + arow) * AST
                                               + ks * 16 + acolb) * 2));
            ldm_x4t(Bf, YB + (uint32_t)(((ks * 16 + brow) * YST
                                         + jw + bcol) * 2));
            mma_f16(acc[0][0], a0, Bf);
            mma_f16(acc[0][1], a0, Bf + 2);
            mma_f16(acc[1][0], a1, Bf);
            mma_f16(acc[1][1], a1, Bf + 2);
        }

        float* ob = out + (((size_t)n * CC + c) * VV) * TT + tt0;
        #pragma unroll
        for (int m = 0; m < 2; ++m)
            #pragma unroll
            for (int t = 0; t < 2; ++t) {
                int v0 = m * 16 + r4;
                int jc = jw + t * 8 + q2;
                if (v0 < VV)
                    *(float2*)(ob + (size_t)v0 * TT + jc) =
                        make_float2(acc[m][t][0], acc[m][t][1]);
                int v1 = v0 + 8;
                if (v1 < VV)
                    *(float2*)(ob + (size_t)v1 * TT + jc) =
                        make_float2(acc[m][t][2], acc[m][t][3]);
            }

        if (ci < 7) {
            char* yd = sm + S2_Y0 + ((ci & 1) ^ 1) * YBUF;
            #pragma unroll
            for (int s = 0; s < 5; ++s)
                *(uint4*)(yd + (lr[s] * YST + lch[s] * 8) * 2) = pf[s];
        }
    }
}

// ---------------------------------------------------------------------------
extern "C" void kernel_launch(void* const* d_in, const int* in_sizes, int n_in,
                              void* d_out, int out_size)
{
    const float* x  = (const float*)d_in[0];
    const float* Wg = (const float*)d_in[1];
    const float* Ag = (const float*)d_in[2];
    float* out = (float*)d_out;

    cudaFuncSetAttribute(stage1_mma,
                         cudaFuncAttributeMaxDynamicSharedMemorySize, S1_TOT);
    cudaFuncSetAttribute(stage2_mma,
                         cudaFuncAttributeMaxDynamicSharedMemorySize, S2_TOT);

    dim3 g1(NT / 256, VV);            // (128, 25)
    stage1_mma<<<g1, 256, S1_TOT>>>(x, Wg);

    dim3 g2(NT / JT, 8);              // (256, 8)
    stage2_mma<<<g2, 256, S2_TOT>>>(Ag, out);
}

// round 16
// speedup vs baseline: 1.2864x; 1.2864x over previous
#include <cuda_runtime.h>
#include <cuda_fp16.h>
#include <cstdint>
#include <cstddef>

// Shapes: x[32,64,25,1024], W[25,192,64], A[3,25,25], out[32,64,25,1024]
// Stage 1 (HMMA fp16): Yh[c*75 + k*25 + w][j] = sum_c' W[w,c*3+k,c'] x[n,c',w,t]
//   R14 structure (128-j per CTA, two 64-j halves, X reg-prefetch, single sS)
//   + fully vectorized 16B memory ops (LDG.128 / LDS.128 / STG.128).
// Stage 2 (HMMA fp16, single-pass A): out[n,c,v,t] = sum_r A[v,r]*Yh[c*75+r][j]
//   (R14 version, unchanged: at its bandwidth floor)

#define NB 32
#define CC 64
#define VV 25
#define TT 1024
#define KK 3
#define OO 192
#define NT 32768
#define WS1 72            /* stage1 padded row stride (halves) */

// 315 MB fp16 scratch for Y.
__device__ unsigned short g_Yh[(size_t)VV * OO * NT];

// stage1 smem layout (dynamic, 73728 B -> 2 CTAs/SM)
#define S1_W   0
#define S1_X0  27648
#define S1_X1  36864
#define S1_S   46080
#define S1_TOT 73728

// stage2 smem layout (dynamic, 49152 B)
#define AST    88
#define YST    136
#define YBUF   (80 * YST * 2)     /* 21760 */
#define S2_A   0
#define S2_Y0  5632
#define S2_TOT (5632 + 2 * YBUF)  /* 49152 */

// ---------------------------------------------------------------------------
__device__ __forceinline__ uint32_t smem_u32(const void* p) {
    uint32_t a;
    asm("{ .reg .u64 t; cvta.to.shared.u64 t, %1; cvt.u32.u64 %0, t; }"
        : "=r"(a) : "l"(p));
    return a;
}
__device__ __forceinline__ void ldm_x4(uint32_t a[4], uint32_t addr) {
    asm volatile("ldmatrix.sync.aligned.m8n8.x4.shared.b16 {%0,%1,%2,%3}, [%4];"
        : "=r"(a[0]), "=r"(a[1]), "=r"(a[2]), "=r"(a[3]) : "r"(addr));
}
__device__ __forceinline__ void ldm_x2t(uint32_t b[2], uint32_t addr) {
    asm volatile("ldmatrix.sync.aligned.m8n8.x2.trans.shared.b16 {%0,%1}, [%2];"
        : "=r"(b[0]), "=r"(b[1]) : "r"(addr));
}
__device__ __forceinline__ void ldm_x4t(uint32_t a[4], uint32_t addr) {
    asm volatile("ldmatrix.sync.aligned.m8n8.x4.trans.shared.b16 {%0,%1,%2,%3}, [%4];"
        : "=r"(a[0]), "=r"(a[1]), "=r"(a[2]), "=r"(a[3]) : "r"(addr));
}
__device__ __forceinline__ void mma_f16(float c[4], const uint32_t a[4],
                                        const uint32_t b[2]) {
    asm volatile("mma.sync.aligned.m16n8k16.row.col.f32.f16.f16.f32 "
        "{%0,%1,%2,%3}, {%4,%5,%6,%7}, {%8,%9}, {%0,%1,%2,%3};"
        : "+f"(c[0]), "+f"(c[1]), "+f"(c[2]), "+f"(c[3])
        : "r"(a[0]), "r"(a[1]), "r"(a[2]), "r"(a[3]), "r"(b[0]), "r"(b[1]));
}
// pack 4 floats -> 4 halves (two half2) as uint2
__device__ __forceinline__ uint2 pack4h(float4 v) {
    union { __half2 h[2]; uint2 u; } pk;
    pk.h[0] = __floats2half2_rn(v.x, v.y);
    pk.h[1] = __floats2half2_rn(v.z, v.w);
    return pk.u;
}

// ---------------------------------------------------------------------------
// Stage 1 (R14 structure, vectorized memory ops)
// ---------------------------------------------------------------------------
__global__ __launch_bounds__(256, 2) void stage1_mma(
    const float* __restrict__ x, const float* __restrict__ Wg)
{
    extern __shared__ char sm[];
    const uint32_t sb = smem_u32(sm);

    const int tid = threadIdx.x;
    const int w   = blockIdx.y;
    const int j0  = blockIdx.x * 128;
    const int n   = j0 >> 10;
    const int t0  = j0 & 1023;

    // ---- W[w] 192x64 fp32 -> fp16, LDG.128 (12 iters) ----
    {
        const float* wg = Wg + (size_t)w * OO * 64;
        #pragma unroll
        for (int i = 0; i < 12; ++i) {
            int idx = tid + i * 256;
            int o = idx >> 4, cp = idx & 15;
            float4 wv = *(const float4*)(wg + (size_t)o * 64 + cp * 4);
            *(uint2*)(sm + S1_W + (o * WS1 + cp * 4) * 2) = pack4h(wv);
        }
    }
    const float* xb = x + (size_t)n * CC * VV * TT + (size_t)w * TT + t0;
    // ---- X half 0, LDG.128 (4 iters) ----
    {
        #pragma unroll
        for (int i = 0; i < 4; ++i) {
            int idx = tid + i * 256;
            int r = idx >> 4, c4 = idx & 15;
            float4 xv = *(const float4*)(xb + (size_t)r * (VV * TT) + c4 * 4);
            *(uint2*)(sm + S1_X0 + (r * WS1 + c4 * 4) * 2) = pack4h(xv);
        }
    }
    __syncthreads();

    const int wid = tid >> 5, lane = tid & 31;
    const int m0 = (wid >> 1) * 48, n0 = (wid & 1) * 32;
    const int arow = lane & 15, acolb = (lane >> 4) * 8, brow = lane & 15;
    const int r4 = lane >> 2, q4 = lane & 3;

    #pragma unroll
    for (int h = 0; h < 2; ++h) {
        const uint32_t XB = sb + (h == 0 ? S1_X0 : S1_X1);

        // prefetch half 1 into registers during half 0's MMA
        float4 xr[4];
        if (h == 0) {
            #pragma unroll
            for (int i = 0; i < 4; ++i) {
                int idx = tid + i * 256;
                int r = idx >> 4, c4 = idx & 15;
                xr[i] = *(const float4*)(xb + 64 + (size_t)r * (VV * TT) + c4 * 4);
            }
        }

        float acc[3][4][4] = {};
        #pragma unroll
        for (int ks = 0; ks < 4; ++ks) {
            uint32_t Af[3][4], Bf[4][2];
            #pragma unroll
            for (int i = 0; i < 3; ++i)
                ldm_x4(Af[i], sb + S1_W + (uint32_t)(((m0 + 16 * i + arow) * WS1
                                                      + ks * 16 + acolb) * 2));
            #pragma unroll
            for (int t = 0; t < 4; ++t)
                ldm_x2t(Bf[t], XB + (uint32_t)(((ks * 16 + brow) * WS1
                                                + n0 + 8 * t) * 2));
            #pragma unroll
            for (int i = 0; i < 3; ++i)
                #pragma unroll
                for (int t = 0; t < 4; ++t)
                    mma_f16(acc[i][t], Af[i], Bf[t]);
        }

        // stage D fragments -> sS
        #pragma unroll
        for (int i = 0; i < 3; ++i)
            #pragma unroll
            for (int t = 0; t < 4; ++t) {
                int row = m0 + 16 * i + r4;
                int col = n0 + 8 * t + 2 * q4;
                *(half2*)(sm + S1_S + (row * WS1 + col) * 2) =
                    __floats2half2_rn(acc[i][t][0], acc[i][t][1]);
                *(half2*)(sm + S1_S + ((row + 8) * WS1 + col) * 2) =
                    __floats2half2_rn(acc[i][t][2], acc[i][t][3]);
            }

        // store prefetched X half 1
        if (h == 0) {
            #pragma unroll
            for (int i = 0; i < 4; ++i) {
                int idx = tid + i * 256;
                int r = idx >> 4, c4 = idx & 15;
                *(uint2*)(sm + S1_X1 + (r * WS1 + c4 * 4) * 2) = pack4h(xr[i]);
            }
        }
        __syncthreads();

        // coalesced copy: 192 rows x 128 B, LDS.128 + STG.128 (6 iters)
        #pragma unroll
        for (int i = 0; i < 6; ++i) {
            int idx = tid + i * 256;
            int row = idx >> 3;           // 8 x 16B chunks per row
            int ch  = idx & 7;
            uint4 val = *(uint4*)(sm + S1_S + row * (WS1 * 2) + ch * 16);
            int cch = row / 3;
            int kk  = row - 3 * cch;
            size_t yrow = (size_t)(cch * 75 + kk * VV + w);
            *(uint4*)((char*)g_Yh + (yrow * NT + j0 + h * 64) * 2 + ch * 16) = val;
        }
        __syncthreads();
    }
}

// ---------------------------------------------------------------------------
// Stage 2 (unchanged from R14): single-pass fp16 A, double-buffered sY.
// ---------------------------------------------------------------------------
#define JT 128

__global__ __launch_bounds__(256) void stage2_mma(
    const float* __restrict__ Ag, float* __restrict__ out)
{
    extern __shared__ char sm[];
    const uint32_t sb = smem_u32(sm);
    __half* sA = (__half*)(sm + S2_A);

    const int tid = threadIdx.x;
    const int j0  = blockIdx.x * JT;
    const int c0  = blockIdx.y * 8;
    const int n   = j0 >> 10;
    const int tt0 = j0 & 1023;

    for (int i = tid; i < 80 * 32; i += 256) {
        int r = i >> 5, v = i & 31;
        float a = (r < 75 && v < 25) ? Ag[r * 25 + v] : 0.0f;
        sA[v * AST + r] = __float2half_rn(a);
    }

    const int wid  = tid >> 5, lane = tid & 31;
    const int jw   = wid * 16;
    const int arow = lane & 15, acolb = (lane >> 4) * 8;
    const int brow = lane & 15, bcol = (lane >> 4) * 8;
    const int r4   = lane >> 2, q2 = (lane & 3) * 2;

    int lr[5], lch[5];
    #pragma unroll
    for (int s = 0; s < 5; ++s) {
        int i = tid + s * 256;
        lr[s]  = i >> 4;
        lch[s] = i & 15;
    }

    uint4 pf[5];
    {
        const char* yb = (const char*)g_Yh + ((size_t)c0 * 75 * NT + j0) * 2;
        #pragma unroll
        for (int s = 0; s < 5; ++s)
            pf[s] = (lr[s] < 75)
                ? *(const uint4*)(yb + (size_t)lr[s] * NT * 2 + lch[s] * 16)
                : make_uint4(0u, 0u, 0u, 0u);
    }
    #pragma unroll
    for (int s = 0; s < 5; ++s)
        *(uint4*)(sm + S2_Y0 + (lr[s] * YST + lch[s] * 8) * 2) = pf[s];

    for (int ci = 0; ci < 8; ++ci) {
        const int c = c0 + ci;
        const uint32_t YB = sb + S2_Y0 + (uint32_t)((ci & 1) * YBUF);

        __syncthreads();

        if (ci < 7) {
            const char* yb = (const char*)g_Yh
                           + ((size_t)(c + 1) * 75 * NT + j0) * 2;
            #pragma unroll
            for (int s = 0; s < 5; ++s)
                pf[s] = (lr[s] < 75)
                    ? *(const uint4*)(yb + (size_t)lr[s] * NT * 2 + lch[s] * 16)
                    : make_uint4(0u, 0u, 0u, 0u);
        }

        float acc[2][2][4] = {};
        #pragma unroll
        for (int ks = 0; ks < 5; ++ks) {
            uint32_t a0[4], a1[4], Bf[4];
            ldm_x4(a0, sb + S2_A + (uint32_t)(((arow) * AST
                                               + ks * 16 + acolb) * 2));
            ldm_x4(a1, sb + S2_A + (uint32_t)(((16 + arow) * AST
                                               + ks * 16 + acolb) * 2));
            ldm_x4t(Bf, YB + (uint32_t)(((ks * 16 + brow) * YST
                                         + jw + bcol) * 2));
            mma_f16(acc[0][0], a0, Bf);
            mma_f16(acc[0][1], a0, Bf + 2);
            mma_f16(acc[1][0], a1, Bf);
            mma_f16(acc[1][1], a1, Bf + 2);
        }

        float* ob = out + (((size_t)n * CC + c) * VV) * TT + tt0;
        #pragma unroll
        for (int m = 0; m < 2; ++m)
            #pragma unroll
            for (int t = 0; t < 2; ++t) {
                int v0 = m * 16 + r4;
                int jc = jw + t * 8 + q2;
                if (v0 < VV)
                    *(float2*)(ob + (size_t)v0 * TT + jc) =
                        make_float2(acc[m][t][0], acc[m][t][1]);
                int v1 = v0 + 8;
                if (v1 < VV)
                    *(float2*)(ob + (size_t)v1 * TT + jc) =
                        make_float2(acc[m][t][2], acc[m][t][3]);
            }

        if (ci < 7) {
            char* yd = sm + S2_Y0 + ((ci & 1) ^ 1) * YBUF;
            #pragma unroll
            for (int s = 0; s < 5; ++s)
                *(uint4*)(yd + (lr[s] * YST + lch[s] * 8) * 2) = pf[s];
        }
    }
}

// ---------------------------------------------------------------------------
extern "C" void kernel_launch(void* const* d_in, const int* in_sizes, int n_in,
                              void* d_out, int out_size)
{
    const float* x  = (const float*)d_in[0];
    const float* Wg = (const float*)d_in[1];
    const float* Ag = (const float*)d_in[2];
    float* out = (float*)d_out;

    cudaFuncSetAttribute(stage1_mma,
                         cudaFuncAttributeMaxDynamicSharedMemorySize, S1_TOT);
    cudaFuncSetAttribute(stage2_mma,
                         cudaFuncAttributeMaxDynamicSharedMemorySize, S2_TOT);

    dim3 g1(NT / 128, VV);            // (256, 25)
    stage1_mma<<<g1, 256, S1_TOT>>>(x, Wg);

    dim3 g2(NT / JT, 8);              // (256, 8)
    stage2_mma<<<g2, 256, S2_TOT>>>(Ag, out);
}